// round 5
// baseline (speedup 1.0000x reference)
#include <cuda_runtime.h>

#define N    2048
#define DIM  1024
#define DCLI 64

// ---- device scratch (no allocations allowed) ----
__device__ float g_xim[N * DIM];          // normalized phi_im
__device__ float g_xcli[N * DCLI];        // normalized phi_cli
__device__ unsigned char g_mask[3][N];    // m0, m1, m2
__device__ unsigned long long g_minkey[6];
__device__ int g_isI32;                   // 1 if t/traumatic are int32, 0 if int64

// monotone order-preserving float<->uint encoding (ascending)
__device__ __forceinline__ unsigned int enc_f(float f) {
    unsigned int b = __float_as_uint(f);
    return (b & 0x80000000u) ? ~b : (b | 0x80000000u);
}
__device__ __forceinline__ float dec_f(unsigned int e) {
    unsigned int b = (e & 0x80000000u) ? (e ^ 0x80000000u) : ~e;
    return __uint_as_float(b);
}
__device__ __forceinline__ unsigned long long ullmin2(unsigned long long a, unsigned long long b) {
    return a < b ? a : b;
}

// ---- row L2 normalization ----
__global__ void norm_im(const float* __restrict__ x) {
    int row = blockIdx.x;
    int t = threadIdx.x;                          // 256 threads, 4 floats each
    float4 a = ((const float4*)(x + (size_t)row * DIM))[t];
    float ss = a.x * a.x + a.y * a.y + a.z * a.z + a.w * a.w;
    #pragma unroll
    for (int o = 16; o; o >>= 1) ss += __shfl_xor_sync(0xffffffffu, ss, o);
    __shared__ float sred[8];
    if ((t & 31) == 0) sred[t >> 5] = ss;
    __syncthreads();
    __shared__ float stot;
    if (t == 0) {
        float s = 0.f;
        #pragma unroll
        for (int w = 0; w < 8; w++) s += sred[w];
        stot = s;
    }
    __syncthreads();
    float inv = 1.0f / fmaxf(sqrtf(stot), 1e-12f);
    ((float4*)(g_xim + (size_t)row * DIM))[t] =
        make_float4(a.x * inv, a.y * inv, a.z * inv, a.w * inv);
}

__global__ void norm_cli(const float* __restrict__ x) {
    int row = blockIdx.x;
    int t = threadIdx.x;                          // 32 threads, 2 floats each
    float2 a = ((const float2*)(x + (size_t)row * DCLI))[t];
    float ss = a.x * a.x + a.y * a.y;
    #pragma unroll
    for (int o = 16; o; o >>= 1) ss += __shfl_xor_sync(0xffffffffu, ss, o);
    float inv = 1.0f / fmaxf(sqrtf(ss), 1e-12f);
    ((float2*)(g_xcli + (size_t)row * DCLI))[t] = make_float2(a.x * inv, a.y * inv);
}

// ---- int64 vs int32 dtype detection (jax silently downcasts int64 -> int32) ----
// Read ONLY the first 4096 int32 words of t: exactly the whole buffer if int32
// (N*2 elements), the first half if int64 — safe under both interpretations.
// int64-LE => every odd word is a zero high-word (values are 0..2).
// int32    => odd words are t[i,1] samples, nonzero w.p. ~1-(1/3)^2048.
__global__ void detect_dtype(const int* __restrict__ t32) {
    int t = threadIdx.x;
    int nz = 0;
    for (int w = 2 * t + 1; w < 2 * N; w += 2 * 256)
        nz |= (t32[w] != 0);
    nz = __syncthreads_or(nz);
    if (t == 0) g_isI32 = nz;
}

__global__ void build_masks(const int* __restrict__ t32, const int* __restrict__ tr32) {
    int i = blockIdx.x * 256 + threadIdx.x;
    int i32 = g_isI32;
    if (i < N) {
        int t1, tr;
        if (i32) { t1 = t32[2 * i + 1]; tr = tr32[i]; }
        else     { t1 = t32[4 * i + 2]; tr = tr32[2 * i]; }  // low words (values are 0..2)
        g_mask[0][i] = (unsigned char)((t1 == 0) && (tr == 1));
        g_mask[1][i] = (unsigned char)(t1 == 1);
        g_mask[2][i] = (unsigned char)(t1 == 2);
    }
    if (blockIdx.x == 0 && threadIdx.x < 6)
        g_minkey[threadIdx.x] = 0xFF80000000000000ull;  // enc(+inf)<<32 | 0
}

// ---- fused GEMM (S = Xn Xn^T tile) + masked scatter + min/argmin ----
// BM=BN=64, BK=16, 256 threads, 4x4 micro-tile per thread.
template <int D, int MB>
__global__ void __launch_bounds__(256) simgemm(float* __restrict__ out) {
    const float* __restrict__ Xn = (D == DIM) ? g_xim : g_xcli;
    __shared__ float As[16][64];
    __shared__ float Bs[16][64];
    __shared__ unsigned long long smk[8];

    const int i0 = blockIdx.y * 64, j0 = blockIdx.x * 64;
    const int t = threadIdx.x;
    const int lr = t >> 2;            // 0..63 row within tile to load
    const int ls = (t & 3) * 4;       // 0,4,8,12 k-segment
    const int tx = t & 15, ty = t >> 4;

    float acc[4][4];
    #pragma unroll
    for (int m = 0; m < 4; m++)
        #pragma unroll
        for (int n = 0; n < 4; n++) acc[m][n] = 0.f;

    const float* Arow = Xn + (size_t)(i0 + lr) * D + ls;
    const float* Brow = Xn + (size_t)(j0 + lr) * D + ls;

    for (int k0 = 0; k0 < D; k0 += 16) {
        float4 a = *(const float4*)(Arow + k0);
        float4 b = *(const float4*)(Brow + k0);
        As[ls + 0][lr] = a.x; As[ls + 1][lr] = a.y; As[ls + 2][lr] = a.z; As[ls + 3][lr] = a.w;
        Bs[ls + 0][lr] = b.x; Bs[ls + 1][lr] = b.y; Bs[ls + 2][lr] = b.z; Bs[ls + 3][lr] = b.w;
        __syncthreads();
        #pragma unroll
        for (int kk = 0; kk < 16; kk++) {
            float4 ra = *(const float4*)&As[kk][ty * 4];
            float4 rb = *(const float4*)&Bs[kk][tx * 4];
            acc[0][0] += ra.x * rb.x; acc[0][1] += ra.x * rb.y; acc[0][2] += ra.x * rb.z; acc[0][3] += ra.x * rb.w;
            acc[1][0] += ra.y * rb.x; acc[1][1] += ra.y * rb.y; acc[1][2] += ra.y * rb.z; acc[1][3] += ra.y * rb.w;
            acc[2][0] += ra.z * rb.x; acc[2][1] += ra.z * rb.y; acc[2][2] += ra.z * rb.z; acc[2][3] += ra.z * rb.w;
            acc[3][0] += ra.w * rb.x; acc[3][1] += ra.w * rb.y; acc[3][2] += ra.w * rb.z; acc[3][3] += ra.w * rb.w;
        }
        __syncthreads();
    }

    // epilogue: 3 mask-pairs, write masked values (full coverage), track min keys
    const int ib = i0 + ty * 4;
    const int jb = j0 + tx * 4;
    const int pa[3] = {0, 0, 1};
    const int pb[3] = {1, 2, 2};

    #pragma unroll
    for (int p = 0; p < 3; p++) {
        unsigned long long mk = 0xFFFFFFFFFFFFFFFFull;
        float* po = out + ((size_t)(MB + p) * N + ib) * N + jb;
        bool cb[4];
        #pragma unroll
        for (int n = 0; n < 4; n++) cb[n] = (g_mask[pb[p]][jb + n] != 0);
        #pragma unroll
        for (int m = 0; m < 4; m++) {
            bool am = (g_mask[pa[p]][ib + m] != 0);
            float w[4];
            #pragma unroll
            for (int n = 0; n < 4; n++) {
                bool v = am && cb[n];
                w[n] = v ? acc[m][n] : 0.f;
                if (v) {
                    unsigned long long key =
                        ((unsigned long long)enc_f(acc[m][n]) << 32) |
                        (unsigned int)((ib + m) * N + jb + n);
                    mk = ullmin2(mk, key);
                }
            }
            *(float4*)(po + (size_t)m * N) = make_float4(w[0], w[1], w[2], w[3]);
        }

        // warp shuffle min-reduce, then 8-way shared reduce, one atomic per pair
        #pragma unroll
        for (int o = 16; o; o >>= 1) {
            unsigned long long other = __shfl_xor_sync(0xffffffffu, mk, o);
            mk = ullmin2(mk, other);
        }
        __syncthreads();
        if ((t & 31) == 0) smk[t >> 5] = mk;
        __syncthreads();
        if (t == 0) {
            unsigned long long r = smk[0];
            #pragma unroll
            for (int w = 1; w < 8; w++) r = ullmin2(r, smk[w]);
            atomicMin(&g_minkey[MB + p], r);
        }
    }
}

// ---- finalize: decode keys into min_vals + min_idx (bounds-guarded) ----
__global__ void finalize(float* __restrict__ out, long long out_elems) {
    int i = threadIdx.x;
    if (i < 6) {
        unsigned long long k = g_minkey[i];
        float v = dec_f((unsigned int)(k >> 32));
        unsigned int flat = (unsigned int)(k & 0xFFFFFFFFull);
        long long base = (long long)6 * N * N;
        if (base + i < out_elems)
            out[base + i] = v;
        if (base + 6 + 2 * i + 1 < out_elems) {
            out[base + 6 + 2 * i]     = (float)(flat / N);
            out[base + 6 + 2 * i + 1] = (float)(flat % N);
        }
    }
}

extern "C" void kernel_launch(void* const* d_in, const int* in_sizes, int n_in,
                              void* d_out, int out_size) {
    const float* phi_im  = (const float*)d_in[0];
    const float* phi_cli = (const float*)d_in[1];
    const int*   t32     = (const int*)d_in[2];
    const int*   tr32    = (const int*)d_in[3];
    float* out = (float*)d_out;

    norm_im<<<N, 256>>>(phi_im);
    norm_cli<<<N, 32>>>(phi_cli);
    detect_dtype<<<1, 256>>>(t32);
    build_masks<<<N / 256, 256>>>(t32, tr32);

    dim3 grid(N / 64, N / 64);
    simgemm<DIM, 0><<<grid, 256>>>(out);
    simgemm<DCLI, 3><<<grid, 256>>>(out);
    finalize<<<1, 32>>>(out, (long long)out_size);
}

// round 7
// speedup vs baseline: 1.5806x; 1.5806x over previous
#include <cuda_runtime.h>

#define N    2048
#define DIM  1024
#define DCLI 64

// ---- device scratch (no allocations allowed) ----
__device__ float g_xim[N * DIM];          // normalized phi_im
__device__ float g_xcli[N * DCLI];        // normalized phi_cli
__device__ int g_idx[3][N];               // compacted original indices per class
__device__ int g_cnt[3];                  // class sizes
__device__ unsigned long long g_minkey[6];

// monotone order-preserving float<->uint encoding (ascending)
__device__ __forceinline__ unsigned int enc_f(float f) {
    unsigned int b = __float_as_uint(f);
    return (b & 0x80000000u) ? ~b : (b | 0x80000000u);
}
__device__ __forceinline__ float dec_f(unsigned int e) {
    unsigned int b = (e & 0x80000000u) ? (e ^ 0x80000000u) : ~e;
    return __uint_as_float(b);
}
__device__ __forceinline__ unsigned long long ullmin2(unsigned long long a, unsigned long long b) {
    return a < b ? a : b;
}

// ---- row L2 normalization ----
__global__ void norm_im(const float* __restrict__ x) {
    int row = blockIdx.x;
    int t = threadIdx.x;                          // 256 threads, 4 floats each
    float4 a = ((const float4*)(x + (size_t)row * DIM))[t];
    float ss = a.x * a.x + a.y * a.y + a.z * a.z + a.w * a.w;
    #pragma unroll
    for (int o = 16; o; o >>= 1) ss += __shfl_xor_sync(0xffffffffu, ss, o);
    __shared__ float sred[8];
    if ((t & 31) == 0) sred[t >> 5] = ss;
    __syncthreads();
    __shared__ float stot;
    if (t == 0) {
        float s = 0.f;
        #pragma unroll
        for (int w = 0; w < 8; w++) s += sred[w];
        stot = s;
    }
    __syncthreads();
    float inv = 1.0f / fmaxf(sqrtf(stot), 1e-12f);
    ((float4*)(g_xim + (size_t)row * DIM))[t] =
        make_float4(a.x * inv, a.y * inv, a.z * inv, a.w * inv);
}

__global__ void norm_cli(const float* __restrict__ x) {
    int row = blockIdx.x;
    int t = threadIdx.x;                          // 32 threads, 2 floats each
    float2 a = ((const float2*)(x + (size_t)row * DCLI))[t];
    float ss = a.x * a.x + a.y * a.y;
    #pragma unroll
    for (int o = 16; o; o >>= 1) ss += __shfl_xor_sync(0xffffffffu, ss, o);
    float inv = 1.0f / fmaxf(sqrtf(ss), 1e-12f);
    ((float2*)(g_xcli + (size_t)row * DCLI))[t] = make_float2(a.x * inv, a.y * inv);
}

// ---- dtype detect + mask build + deterministic compaction (one block) ----
// dtype probe reads ONLY the first 2N int32 words of t (whole buffer if int32,
// first half if int64). int64-LE => odd words are zero high-words.
__global__ void build_sets(const int* __restrict__ t32, const int* __restrict__ tr32) {
    const int t = threadIdx.x;
    const int lane = t & 31, warp = t >> 5;
    __shared__ int wsum[3][8];
    __shared__ int base[3];

    int nz = 0;
    for (int w = 2 * t + 1; w < 2 * N; w += 2 * 256)
        nz |= (t32[w] != 0);
    nz = __syncthreads_or(nz);
    const int i32 = nz;

    if (t < 3) base[t] = 0;
    if (t < 6) g_minkey[t] = 0xFF80000000000000ull;  // enc(+inf)<<32 | 0
    __syncthreads();

    for (int chunk = 0; chunk < N; chunk += 256) {
        int i = chunk + t;
        int t1, tr;
        if (i32) { t1 = t32[2 * i + 1]; tr = tr32[i]; }
        else     { t1 = t32[4 * i + 2]; tr = tr32[2 * i]; }  // low words (vals 0..2)
        bool mem[3];
        mem[0] = (t1 == 0) && (tr == 1);
        mem[1] = (t1 == 1);
        mem[2] = (t1 == 2);

        int wpre[3];
        #pragma unroll
        for (int c = 0; c < 3; c++) {
            unsigned b = __ballot_sync(0xffffffffu, mem[c]);
            wpre[c] = __popc(b & ((1u << lane) - 1u));
            if (lane == 0) wsum[c][warp] = __popc(b);
        }
        __syncthreads();
        int ctot[3];
        #pragma unroll
        for (int c = 0; c < 3; c++) {
            int woff = 0;
            #pragma unroll
            for (int w = 0; w < 8; w++) if (w < warp) woff += wsum[c][w];
            int tot = 0;
            #pragma unroll
            for (int w = 0; w < 8; w++) tot += wsum[c][w];
            if (mem[c]) g_idx[c][base[c] + woff + wpre[c]] = i;
            ctot[c] = tot;
        }
        __syncthreads();
        if (t == 0) {
            #pragma unroll
            for (int c = 0; c < 3; c++) base[c] += ctot[c];
        }
        __syncthreads();
    }
    if (t < 3) g_cnt[t] = base[t];
}

// ---- compacted pair-GEMM + scatter + min/argmin ----
// grid (32,32,6): z = modality*3 + pair. 64x64 tiles over compacted rectangles,
// blocks beyond the data-dependent counts exit immediately.
__global__ void __launch_bounds__(256) pairgemm(float* __restrict__ out) {
    const int z = blockIdx.z;
    const int mod = z / 3;          // 0: im (D=1024), 1: cli (D=64)
    const int p = z % 3;
    const int pa[3] = {0, 0, 1};
    const int pb[3] = {1, 2, 2};

    const int ca = g_cnt[pa[p]];
    const int cb = g_cnt[pb[p]];
    const int i0 = blockIdx.y * 64, j0 = blockIdx.x * 64;
    if (i0 >= ca || j0 >= cb) return;

    const int* __restrict__ idxA = g_idx[pa[p]];
    const int* __restrict__ idxB = g_idx[pb[p]];
    const float* __restrict__ Xn = (mod == 0) ? g_xim : g_xcli;
    const int D = (mod == 0) ? DIM : DCLI;

    __shared__ float As[16][64];
    __shared__ float Bs[16][64];
    __shared__ unsigned long long smk[8];

    const int t = threadIdx.x;
    const int lr = t >> 2;            // 0..63 row within tile to load
    const int ls = (t & 3) * 4;       // 0,4,8,12 k-segment
    const int tx = t & 15, ty = t >> 4;

    const int ga = idxA[min(i0 + lr, ca - 1)];
    const int gb = idxB[min(j0 + lr, cb - 1)];
    const float* Arow = Xn + (size_t)ga * D + ls;
    const float* Brow = Xn + (size_t)gb * D + ls;

    float acc[4][4];
    #pragma unroll
    for (int m = 0; m < 4; m++)
        #pragma unroll
        for (int n = 0; n < 4; n++) acc[m][n] = 0.f;

    for (int k0 = 0; k0 < D; k0 += 16) {
        float4 a = *(const float4*)(Arow + k0);
        float4 b = *(const float4*)(Brow + k0);
        As[ls + 0][lr] = a.x; As[ls + 1][lr] = a.y; As[ls + 2][lr] = a.z; As[ls + 3][lr] = a.w;
        Bs[ls + 0][lr] = b.x; Bs[ls + 1][lr] = b.y; Bs[ls + 2][lr] = b.z; Bs[ls + 3][lr] = b.w;
        __syncthreads();
        #pragma unroll
        for (int kk = 0; kk < 16; kk++) {
            float4 ra = *(const float4*)&As[kk][ty * 4];
            float4 rb = *(const float4*)&Bs[kk][tx * 4];
            acc[0][0] += ra.x * rb.x; acc[0][1] += ra.x * rb.y; acc[0][2] += ra.x * rb.z; acc[0][3] += ra.x * rb.w;
            acc[1][0] += ra.y * rb.x; acc[1][1] += ra.y * rb.y; acc[1][2] += ra.y * rb.z; acc[1][3] += ra.y * rb.w;
            acc[2][0] += ra.z * rb.x; acc[2][1] += ra.z * rb.y; acc[2][2] += ra.z * rb.z; acc[2][3] += ra.z * rb.w;
            acc[3][0] += ra.w * rb.x; acc[3][1] += ra.w * rb.y; acc[3][2] += ra.w * rb.z; acc[3][3] += ra.w * rb.w;
        }
        __syncthreads();
    }

    // epilogue: scatter valid entries to original coordinates + min-key
    const int ib = i0 + ty * 4;
    const int jb = j0 + tx * 4;
    int gi[4], gj[4];
    #pragma unroll
    for (int m = 0; m < 4; m++) gi[m] = (ib + m < ca) ? idxA[ib + m] : -1;
    #pragma unroll
    for (int n = 0; n < 4; n++) gj[n] = (jb + n < cb) ? idxB[jb + n] : -1;

    float* __restrict__ po = out + (size_t)z * N * N;
    unsigned long long mk = 0xFFFFFFFFFFFFFFFFull;
    #pragma unroll
    for (int m = 0; m < 4; m++) {
        if (gi[m] < 0) continue;
        #pragma unroll
        for (int n = 0; n < 4; n++) {
            if (gj[n] < 0) continue;
            unsigned int off = (unsigned int)(gi[m] * N + gj[n]);
            po[off] = acc[m][n];
            unsigned long long key =
                ((unsigned long long)enc_f(acc[m][n]) << 32) | off;
            mk = ullmin2(mk, key);
        }
    }

    // warp shuffle min-reduce, then 8-way shared reduce, one atomic per block
    #pragma unroll
    for (int o = 16; o; o >>= 1) {
        unsigned long long other = __shfl_xor_sync(0xffffffffu, mk, o);
        mk = ullmin2(mk, other);
    }
    if ((t & 31) == 0) smk[t >> 5] = mk;
    __syncthreads();
    if (t == 0) {
        unsigned long long r = smk[0];
        #pragma unroll
        for (int w = 1; w < 8; w++) r = ullmin2(r, smk[w]);
        atomicMin(&g_minkey[z], r);
    }
}

// ---- finalize: decode keys into min_vals + min_idx (bounds-guarded) ----
__global__ void finalize(float* __restrict__ out, long long out_elems) {
    int i = threadIdx.x;
    if (i < 6) {
        unsigned long long k = g_minkey[i];
        float v = dec_f((unsigned int)(k >> 32));
        unsigned int flat = (unsigned int)(k & 0xFFFFFFFFull);
        long long base = (long long)6 * N * N;
        if (base + i < out_elems)
            out[base + i] = v;
        if (base + 6 + 2 * i + 1 < out_elems) {
            out[base + 6 + 2 * i]     = (float)(flat / N);
            out[base + 6 + 2 * i + 1] = (float)(flat % N);
        }
    }
}

extern "C" void kernel_launch(void* const* d_in, const int* in_sizes, int n_in,
                              void* d_out, int out_size) {
    const float* phi_im  = (const float*)d_in[0];
    const float* phi_cli = (const float*)d_in[1];
    const int*   t32     = (const int*)d_in[2];
    const int*   tr32    = (const int*)d_in[3];
    float* out = (float*)d_out;

    // background zeros for all 6 masked matrices (capturable memset node)
    cudaMemsetAsync(d_out, 0, (size_t)out_size * sizeof(float), 0);

    norm_im<<<N, 256>>>(phi_im);
    norm_cli<<<N, 32>>>(phi_cli);
    build_sets<<<1, 256>>>(t32, tr32);

    pairgemm<<<dim3(32, 32, 6), 256>>>(out);
    finalize<<<1, 32>>>(out, (long long)out_size);
}